// round 2
// baseline (speedup 1.0000x reference)
#include <cuda_runtime.h>
#include <cuda_bf16.h>
#include <stdint.h>

// ---------------------------------------------------------------------------
// GraphTripleConv: B=32, O=512, T=2048, D=128, HIDDEN=256, PRED_OUT=128
//
// Pipeline:
//   X  = gather([obj[s], pred, obj[o]])            (65536 x 384)
//   H  = relu(X @ W1a + b1a)                       (65536 x 256)
//   NT = relu(H @ W2a + b2a)                       (65536 x 640)
//   new_p = NT[:,256:384]  -> d_out[2097152:]
//   pooled[b,s] += NT[:,0:256]*m ; pooled[b,o] += NT[:,384:640]*m ; counts += m
//   pooled /= counts (where >0)
//   H2 = relu(pooled @ W1b + b1b)                  (16384 x 256)
//   new_obj = relu(H2 @ W2b + b2b) -> d_out[0:2097152]
// ---------------------------------------------------------------------------

#define B_    32
#define O_    512
#define T_    2048
#define D_    128
#define HID   256
#define POUT  128
#define OUT1  640
#define IN1   384
#define NTROW (B_*T_)   // 65536
#define NOROW (B_*O_)   // 16384

// Scratch (static device globals -- allocation-free)
__device__ float g_X[(size_t)NTROW * IN1];
__device__ float g_H[(size_t)NTROW * HID];
__device__ float g_NT[(size_t)NTROW * OUT1];
__device__ float g_POOL[(size_t)NOROW * HID];
__device__ float g_CNT[NOROW];
__device__ float g_H2[(size_t)NOROW * HID];
__device__ float g_MASK[NTROW];
__device__ int   g_mode;   // 0=f32, 1=i32, 2=u8/i8, 3=bf16

// ---------------------------------------------------------------------------
// pred_indicators dtype sniffer: values are only {0,1} in some dtype.
// Scan 16384 32-bit words (64KB -- safe lower bound for every candidate dtype).
// ---------------------------------------------------------------------------
__global__ void detect_kernel(const unsigned* __restrict__ w, int nwords) {
    __shared__ int sf32, sbf16, sother;
    if (threadIdx.x == 0) { sf32 = 0; sbf16 = 0; sother = 0; }
    __syncthreads();
    for (int i = threadIdx.x; i < nwords; i += blockDim.x) {
        unsigned v = w[i];
        if (v == 0x3F800000u) sf32 = 1;
        unsigned lo = v & 0xFFFFu, hi = v >> 16;
        bool bfp = (lo == 0u || lo == 0x3F80u) && (hi == 0u || hi == 0x3F80u);
        if (bfp && (lo == 0x3F80u || hi == 0x3F80u)) sbf16 = 1;
        if (v != 0u && v != 1u && !bfp && v != 0x3F800000u) sother = 1;
    }
    __syncthreads();
    if (threadIdx.x == 0) {
        int m;
        if (sf32) m = 0;
        else if (sbf16) m = 3;
        else if (sother) m = 2;
        else m = 1;
        g_mode = m;
    }
}

__global__ void build_mask_kernel(const void* __restrict__ p) {
    int i = blockIdx.x * blockDim.x + threadIdx.x;
    if (i >= NTROW) return;
    int mode = g_mode;
    float v;
    if (mode == 0)      v = ((const float*)p)[i];
    else if (mode == 1) v = (float)((const int*)p)[i];
    else if (mode == 2) v = (float)((const unsigned char*)p)[i];
    else                v = __bfloat162float(((const __nv_bfloat16*)p)[i]);
    g_MASK[i] = v;
}

// ---------------------------------------------------------------------------
// zero pooled + counts
// ---------------------------------------------------------------------------
__global__ void zero_kernel() {
    int i = blockIdx.x * blockDim.x + threadIdx.x;
    if (i < NOROW * HID) g_POOL[i] = 0.0f;
    if (i < NOROW)       g_CNT[i]  = 0.0f;
}

// ---------------------------------------------------------------------------
// gather: X[t] = [obj[b,s], pred[b,t], obj[b,o]]   (96 float4 per row)
// ---------------------------------------------------------------------------
__global__ void gather_kernel(const float* __restrict__ obj,
                              const float* __restrict__ pred,
                              const int*   __restrict__ edges) {
    int t = blockIdx.x;        // 0..65535
    int b = t >> 11;           // / 2048
    int s = edges[2 * t];
    int o = edges[2 * t + 1];
    int j = threadIdx.x;       // 0..95
    float4 v;
    if (j < 32)
        v = ((const float4*)(obj + ((size_t)(b * O_ + s)) * D_))[j];
    else if (j < 64)
        v = ((const float4*)(pred + (size_t)t * D_))[j - 32];
    else
        v = ((const float4*)(obj + ((size_t)(b * O_ + o)) * D_))[j - 64];
    ((float4*)(g_X + (size_t)t * IN1))[j] = v;
}

// ---------------------------------------------------------------------------
// SGEMM: C = relu(A @ B + bias)
//   A: MxK row-major, B: KxN row-major, C: MxN row-major
//   BM=BN=128, BK=16, 256 threads, 8x8 per thread.
//   Requires M%128==0, N%128==0, K%16==0 (all shapes here comply).
// ---------------------------------------------------------------------------
#define BM 128
#define BN 128
#define BK 16
#define TM 8
#define TN 8

__global__ void __launch_bounds__(256, 2)
sgemm_relu(const float* __restrict__ A, const float* __restrict__ B,
           const float* __restrict__ bias, float* __restrict__ C,
           int M, int N, int K) {
    __shared__ float As[BK][BM];
    __shared__ float Bs[BK][BN];

    const int tid  = threadIdx.x;
    const int trow = tid >> 4;   // 0..15
    const int tcol = tid & 15;   // 0..15

    const size_t aBase = (size_t)blockIdx.y * BM * K;
    const float* Bp = B + blockIdx.x * BN;

    float acc[TM][TN];
#pragma unroll
    for (int i = 0; i < TM; i++)
#pragma unroll
        for (int j = 0; j < TN; j++) acc[i][j] = 0.0f;

    for (int k0 = 0; k0 < K; k0 += BK) {
        // A tile: 128x16 = 512 float4, 2 per thread; store transposed As[k][m]
#pragma unroll
        for (int l = tid; l < BM * BK / 4; l += 256) {
            int r  = l >> 2;
            int c4 = (l & 3) << 2;
            float4 v = *(const float4*)(A + aBase + (size_t)r * K + k0 + c4);
            As[c4 + 0][r] = v.x;
            As[c4 + 1][r] = v.y;
            As[c4 + 2][r] = v.z;
            As[c4 + 3][r] = v.w;
        }
        // B tile: 16x128 = 512 float4, 2 per thread
#pragma unroll
        for (int l = tid; l < BK * BN / 4; l += 256) {
            int r  = l >> 5;
            int c4 = (l & 31) << 2;
            *(float4*)&Bs[r][c4] = *(const float4*)(Bp + (size_t)(k0 + r) * N + c4);
        }
        __syncthreads();

#pragma unroll
        for (int kk = 0; kk < BK; kk++) {
            float ra[TM], rb[TN];
            *(float4*)&ra[0] = *(const float4*)&As[kk][trow * TM];
            *(float4*)&ra[4] = *(const float4*)&As[kk][trow * TM + 4];
            *(float4*)&rb[0] = *(const float4*)&Bs[kk][tcol * TN];
            *(float4*)&rb[4] = *(const float4*)&Bs[kk][tcol * TN + 4];
#pragma unroll
            for (int i = 0; i < TM; i++)
#pragma unroll
                for (int j = 0; j < TN; j++)
                    acc[i][j] = fmaf(ra[i], rb[j], acc[i][j]);
        }
        __syncthreads();
    }

    // epilogue: bias + relu, vectorized stores
    const int colBase = blockIdx.x * BN + tcol * TN;
    const int rowBase = blockIdx.y * BM + trow * TM;
    float bv[TN];
#pragma unroll
    for (int j = 0; j < TN; j++) bv[j] = bias[colBase + j];

#pragma unroll
    for (int i = 0; i < TM; i++) {
        float4 v0, v1;
        v0.x = fmaxf(acc[i][0] + bv[0], 0.0f);
        v0.y = fmaxf(acc[i][1] + bv[1], 0.0f);
        v0.z = fmaxf(acc[i][2] + bv[2], 0.0f);
        v0.w = fmaxf(acc[i][3] + bv[3], 0.0f);
        v1.x = fmaxf(acc[i][4] + bv[4], 0.0f);
        v1.y = fmaxf(acc[i][5] + bv[5], 0.0f);
        v1.z = fmaxf(acc[i][6] + bv[6], 0.0f);
        v1.w = fmaxf(acc[i][7] + bv[7], 0.0f);
        float* cp = C + (size_t)(rowBase + i) * N + colBase;
        *(float4*)cp       = v0;
        *(float4*)(cp + 4) = v1;
    }
}

// ---------------------------------------------------------------------------
// scatter: copy new_p to output; masked atomic scatter of new_s/new_o + counts
// ---------------------------------------------------------------------------
__global__ void scatter_kernel(const int* __restrict__ edges,
                               float* __restrict__ out_p) {
    int e   = blockIdx.x;       // 0..65535
    int tid = threadIdx.x;      // 0..255
    int b   = e >> 11;
    const float* __restrict__ row = g_NT + (size_t)e * OUT1;

    if (tid < POUT)
        out_p[(size_t)e * POUT + tid] = row[HID + tid];

    float m = g_MASK[e];
    if (m != 0.0f) {
        int s = edges[2 * e];
        int o = edges[2 * e + 1];
        atomicAdd(&g_POOL[(size_t)(b * O_ + s) * HID + tid], row[tid] * m);
        atomicAdd(&g_POOL[(size_t)(b * O_ + o) * HID + tid], row[HID + POUT + tid] * m);
        if (tid == 0) {
            atomicAdd(&g_CNT[b * O_ + s], m);
            atomicAdd(&g_CNT[b * O_ + o], m);
        }
    }
}

__global__ void finalize_kernel() {
    int i = blockIdx.x * blockDim.x + threadIdx.x;
    if (i >= NOROW * HID) return;
    float c = g_CNT[i >> 8];   // HID == 256
    if (c > 0.0f) g_POOL[i] /= c;
}

// ---------------------------------------------------------------------------
extern "C" void kernel_launch(void* const* d_in, const int* in_sizes, int n_in,
                              void* d_out, int out_size) {
    const float* obj   = (const float*)d_in[0];
    const float* pred  = (const float*)d_in[1];
    const int*   edges = (const int*)  d_in[2];
    const void*  pind  =               d_in[3];
    const float* W1a   = (const float*)d_in[4];
    const float* b1a   = (const float*)d_in[5];
    const float* W2a   = (const float*)d_in[6];
    const float* b2a   = (const float*)d_in[7];
    const float* W1b   = (const float*)d_in[8];
    const float* b1b   = (const float*)d_in[9];
    const float* W2b   = (const float*)d_in[10];
    const float* b2b   = (const float*)d_in[11];

    float* out     = (float*)d_out;
    float* out_obj = out;                                  // (32,512,128)
    float* out_p   = out + (size_t)NOROW * POUT;           // (32,2048,128)

    float *X, *H, *NT, *POOL, *H2;
    cudaGetSymbolAddress((void**)&X,    g_X);
    cudaGetSymbolAddress((void**)&H,    g_H);
    cudaGetSymbolAddress((void**)&NT,   g_NT);
    cudaGetSymbolAddress((void**)&POOL, g_POOL);
    cudaGetSymbolAddress((void**)&H2,   g_H2);

    // mask dtype sniff + mask build
    detect_kernel<<<1, 256>>>((const unsigned*)pind, NTROW / 4);
    build_mask_kernel<<<NTROW / 256, 256>>>(pind);

    // zero pooled/counts
    zero_kernel<<<(NOROW * HID + 255) / 256, 256>>>();

    // gather concat input
    gather_kernel<<<NTROW, 96>>>(obj, pred, edges);

    // MLP-a
    sgemm_relu<<<dim3(HID / BN,  NTROW / BM), 256>>>(X, W1a, b1a, H,  NTROW, HID,  IN1);
    sgemm_relu<<<dim3(OUT1 / BN, NTROW / BM), 256>>>(H, W2a, b2a, NT, NTROW, OUT1, HID);

    // scatter-mean + new_p output
    scatter_kernel<<<NTROW, 256>>>(edges, out_p);
    finalize_kernel<<<(NOROW * HID + 255) / 256, 256>>>();

    // MLP-b (final layer writes straight to d_out)
    sgemm_relu<<<dim3(HID / BN,  NOROW / BM), 256>>>(POOL, W1b, b1b, H2, NOROW, HID, HID);
    sgemm_relu<<<dim3(POUT / BN, NOROW / BM), 256>>>(H2,   W2b, b2b, out_obj, NOROW, POUT, HID);
}

// round 4
// speedup vs baseline: 1.9613x; 1.9613x over previous
#include <cuda_runtime.h>
#include <cuda_bf16.h>
#include <stdint.h>

// ---------------------------------------------------------------------------
// GraphTripleConv: B=32, O=512, T=2048, D=128, HIDDEN=256, PRED_OUT=128
// Round 4 (= round 3 resubmit after infra failure):
// all 4 GEMMs on tensor cores (mma.sync.m16n8k8.tf32, fp32 accum,
// RNA-rounded tf32 operands). Gather / scatter-mean unchanged.
// ---------------------------------------------------------------------------

#define B_    32
#define O_    512
#define T_    2048
#define D_    128
#define HID   256
#define POUT  128
#define OUT1  640
#define IN1   384
#define NTROW (B_*T_)   // 65536
#define NOROW (B_*O_)   // 16384

// Scratch (static device globals -- allocation-free)
__device__ float g_X[(size_t)NTROW * IN1];
__device__ float g_H[(size_t)NTROW * HID];
__device__ float g_NT[(size_t)NTROW * OUT1];
__device__ float g_POOL[(size_t)NOROW * HID];
__device__ float g_CNT[NOROW];
__device__ float g_H2[(size_t)NOROW * HID];
__device__ float g_MASK[NTROW];
__device__ int   g_mode;   // 0=f32, 1=i32, 2=u8/i8, 3=bf16

// ---------------------------------------------------------------------------
// pred_indicators dtype sniffer (values are {0,1} in an unknown dtype)
// ---------------------------------------------------------------------------
__global__ void detect_kernel(const unsigned* __restrict__ w, int nwords) {
    __shared__ int sf32, sbf16, sother;
    if (threadIdx.x == 0) { sf32 = 0; sbf16 = 0; sother = 0; }
    __syncthreads();
    for (int i = threadIdx.x; i < nwords; i += blockDim.x) {
        unsigned v = w[i];
        if (v == 0x3F800000u) sf32 = 1;
        unsigned lo = v & 0xFFFFu, hi = v >> 16;
        bool bfp = (lo == 0u || lo == 0x3F80u) && (hi == 0u || hi == 0x3F80u);
        if (bfp && (lo == 0x3F80u || hi == 0x3F80u)) sbf16 = 1;
        if (v != 0u && v != 1u && !bfp && v != 0x3F800000u) sother = 1;
    }
    __syncthreads();
    if (threadIdx.x == 0) {
        int m;
        if (sf32) m = 0;
        else if (sbf16) m = 3;
        else if (sother) m = 2;
        else m = 1;
        g_mode = m;
    }
}

__global__ void build_mask_kernel(const void* __restrict__ p) {
    int i = blockIdx.x * blockDim.x + threadIdx.x;
    if (i >= NTROW) return;
    int mode = g_mode;
    float v;
    if (mode == 0)      v = ((const float*)p)[i];
    else if (mode == 1) v = (float)((const int*)p)[i];
    else if (mode == 2) v = (float)((const unsigned char*)p)[i];
    else                v = __bfloat162float(((const __nv_bfloat16*)p)[i]);
    g_MASK[i] = v;
}

__global__ void zero_kernel() {
    int i = blockIdx.x * blockDim.x + threadIdx.x;
    if (i < NOROW * HID) g_POOL[i] = 0.0f;
    if (i < NOROW)       g_CNT[i]  = 0.0f;
}

// ---------------------------------------------------------------------------
// gather: X[t] = [obj[b,s], pred[b,t], obj[b,o]]   (96 float4 per row)
// ---------------------------------------------------------------------------
__global__ void gather_kernel(const float* __restrict__ obj,
                              const float* __restrict__ pred,
                              const int*   __restrict__ edges) {
    int t = blockIdx.x;
    int b = t >> 11;
    int s = edges[2 * t];
    int o = edges[2 * t + 1];
    int j = threadIdx.x;
    float4 v;
    if (j < 32)
        v = ((const float4*)(obj + ((size_t)(b * O_ + s)) * D_))[j];
    else if (j < 64)
        v = ((const float4*)(pred + (size_t)t * D_))[j - 32];
    else
        v = ((const float4*)(obj + ((size_t)(b * O_ + o)) * D_))[j - 64];
    ((float4*)(g_X + (size_t)t * IN1))[j] = v;
}

// ---------------------------------------------------------------------------
// TF32 tensor-core GEMM: C = relu(A @ B + bias)
//   A: MxK row-major fp32, B: KxN row-major fp32, C: MxN row-major fp32
//   BM=BN=128, BK=16. 256 threads = 8 warps laid out 4(m) x 2(n).
//   Warp tile 32x64 -> 2 m-frags x 8 n-frags of m16n8k8.
//   Smem: A[m][k] stride 20, B[k][n] stride 132 -> conflict-free A frag LDS,
//   worst-case 2-way on B frag LDS.
//   Double-buffered, one __syncthreads per k-tile.
//   Requires M%128==0, N%128==0, K%16==0 (all shapes comply).
// ---------------------------------------------------------------------------
#define BM 128
#define BN 128
#define BK 16
#define AST 20    // A smem row stride (floats)
#define BST 132   // B smem row stride (floats)

__device__ __forceinline__ uint32_t f2tf(float x) {
    uint32_t r;
    asm("cvt.rna.tf32.f32 %0, %1;" : "=r"(r) : "f"(x));
    return r;
}

__device__ __forceinline__ void mma_tf32(float* c, const uint32_t* a,
                                         uint32_t b0, uint32_t b1) {
    asm volatile(
        "mma.sync.aligned.m16n8k8.row.col.f32.tf32.tf32.f32 "
        "{%0,%1,%2,%3}, {%4,%5,%6,%7}, {%8,%9}, {%0,%1,%2,%3};"
        : "+f"(c[0]), "+f"(c[1]), "+f"(c[2]), "+f"(c[3])
        : "r"(a[0]), "r"(a[1]), "r"(a[2]), "r"(a[3]), "r"(b0), "r"(b1));
}

__global__ void __launch_bounds__(256, 2)
tf32_gemm_relu(const float* __restrict__ A, const float* __restrict__ B,
               const float* __restrict__ bias, float* __restrict__ C,
               int M, int N, int K) {
    __shared__ uint32_t As[2][BM][AST];   // 20480 B
    __shared__ uint32_t Bs[2][BK][BST];   // 16896 B

    const int tid  = threadIdx.x;
    const int warp = tid >> 5;
    const int lane = tid & 31;
    const int g    = lane >> 2;    // groupID 0..7
    const int i4   = lane & 3;     // thread-in-group 0..3
    const int m0   = (warp & 3) * 32;   // warp m-offset in tile
    const int n0   = (warp >> 2) * 64;  // warp n-offset in tile

    const int rowBase = blockIdx.y * BM;
    const int colBase = blockIdx.x * BN;

    // per-thread global-load coordinates (2 float4 each for A and B per tile)
    const int ar0 = tid >> 2, ac0 = (tid & 3) << 2;          // A: l = tid
    const int ar1 = (tid + 256) >> 2, ac1 = ((tid + 256) & 3) << 2;
    const int br0 = tid >> 5, bc0 = (tid & 31) << 2;         // B: l = tid
    const int br1 = (tid + 256) >> 5, bc1 = ((tid + 256) & 31) << 2;

    float c[2][8][4];
#pragma unroll
    for (int mf = 0; mf < 2; mf++)
#pragma unroll
        for (int nf = 0; nf < 8; nf++)
#pragma unroll
            for (int q = 0; q < 4; q++) c[mf][nf][q] = 0.0f;

    // ---- prologue: tile 0 -> smem buf 0
    {
        float4 a0 = *(const float4*)(A + (size_t)(rowBase + ar0) * K + ac0);
        float4 a1 = *(const float4*)(A + (size_t)(rowBase + ar1) * K + ac1);
        float4 b0 = *(const float4*)(B + (size_t)br0 * N + colBase + bc0);
        float4 b1 = *(const float4*)(B + (size_t)br1 * N + colBase + bc1);
        *(uint4*)&As[0][ar0][ac0] = make_uint4(f2tf(a0.x), f2tf(a0.y), f2tf(a0.z), f2tf(a0.w));
        *(uint4*)&As[0][ar1][ac1] = make_uint4(f2tf(a1.x), f2tf(a1.y), f2tf(a1.z), f2tf(a1.w));
        *(uint4*)&Bs[0][br0][bc0] = make_uint4(f2tf(b0.x), f2tf(b0.y), f2tf(b0.z), f2tf(b0.w));
        *(uint4*)&Bs[0][br1][bc1] = make_uint4(f2tf(b1.x), f2tf(b1.y), f2tf(b1.z), f2tf(b1.w));
    }
    __syncthreads();

    int buf = 0;
    for (int k0 = 0; k0 < K; k0 += BK) {
        const bool has_next = (k0 + BK < K);
        float4 an0, an1, bn0, bn1;
        if (has_next) {
            const int kn = k0 + BK;
            an0 = *(const float4*)(A + (size_t)(rowBase + ar0) * K + kn + ac0);
            an1 = *(const float4*)(A + (size_t)(rowBase + ar1) * K + kn + ac1);
            bn0 = *(const float4*)(B + (size_t)(kn + br0) * N + colBase + bc0);
            bn1 = *(const float4*)(B + (size_t)(kn + br1) * N + colBase + bc1);
        }

        // ---- compute on smem[buf]: 2 k-steps of m16n8k8
#pragma unroll
        for (int ks = 0; ks < 2; ks++) {
            const int kk = ks * 8;
            uint32_t a[2][4];
#pragma unroll
            for (int mf = 0; mf < 2; mf++) {
                const int r = m0 + mf * 16 + g;
                a[mf][0] = As[buf][r][kk + i4];
                a[mf][1] = As[buf][r + 8][kk + i4];
                a[mf][2] = As[buf][r][kk + i4 + 4];
                a[mf][3] = As[buf][r + 8][kk + i4 + 4];
            }
#pragma unroll
            for (int nf = 0; nf < 8; nf++) {
                const int cc = n0 + nf * 8 + g;
                const uint32_t b0 = Bs[buf][kk + i4][cc];
                const uint32_t b1 = Bs[buf][kk + i4 + 4][cc];
                mma_tf32(c[0][nf], a[0], b0, b1);
                mma_tf32(c[1][nf], a[1], b0, b1);
            }
        }

        if (has_next) {
            const int nb = buf ^ 1;
            *(uint4*)&As[nb][ar0][ac0] = make_uint4(f2tf(an0.x), f2tf(an0.y), f2tf(an0.z), f2tf(an0.w));
            *(uint4*)&As[nb][ar1][ac1] = make_uint4(f2tf(an1.x), f2tf(an1.y), f2tf(an1.z), f2tf(an1.w));
            *(uint4*)&Bs[nb][br0][bc0] = make_uint4(f2tf(bn0.x), f2tf(bn0.y), f2tf(bn0.z), f2tf(bn0.w));
            *(uint4*)&Bs[nb][br1][bc1] = make_uint4(f2tf(bn1.x), f2tf(bn1.y), f2tf(bn1.z), f2tf(bn1.w));
        }
        __syncthreads();
        buf ^= 1;
    }

    // ---- epilogue: bias + relu, float2 stores
#pragma unroll
    for (int nf = 0; nf < 8; nf++) {
        const int col = colBase + n0 + nf * 8 + 2 * i4;
        const float bx = bias[col], by = bias[col + 1];
#pragma unroll
        for (int mf = 0; mf < 2; mf++) {
            const int r0 = rowBase + m0 + mf * 16 + g;
            float2 v0, v1;
            v0.x = fmaxf(c[mf][nf][0] + bx, 0.0f);
            v0.y = fmaxf(c[mf][nf][1] + by, 0.0f);
            v1.x = fmaxf(c[mf][nf][2] + bx, 0.0f);
            v1.y = fmaxf(c[mf][nf][3] + by, 0.0f);
            *(float2*)(C + (size_t)r0 * N + col)       = v0;
            *(float2*)(C + (size_t)(r0 + 8) * N + col) = v1;
        }
    }
}

// ---------------------------------------------------------------------------
// scatter: copy new_p to output; masked atomic scatter of new_s/new_o + counts
// ---------------------------------------------------------------------------
__global__ void scatter_kernel(const int* __restrict__ edges,
                               float* __restrict__ out_p) {
    int e   = blockIdx.x;
    int tid = threadIdx.x;
    int b   = e >> 11;
    const float* __restrict__ row = g_NT + (size_t)e * OUT1;

    if (tid < POUT)
        out_p[(size_t)e * POUT + tid] = row[HID + tid];

    float m = g_MASK[e];
    if (m != 0.0f) {
        int s = edges[2 * e];
        int o = edges[2 * e + 1];
        atomicAdd(&g_POOL[(size_t)(b * O_ + s) * HID + tid], row[tid] * m);
        atomicAdd(&g_POOL[(size_t)(b * O_ + o) * HID + tid], row[HID + POUT + tid] * m);
        if (tid == 0) {
            atomicAdd(&g_CNT[b * O_ + s], m);
            atomicAdd(&g_CNT[b * O_ + o], m);
        }
    }
}

__global__ void finalize_kernel() {
    int i = blockIdx.x * blockDim.x + threadIdx.x;
    if (i >= NOROW * HID) return;
    float c = g_CNT[i >> 8];   // HID == 256
    if (c > 0.0f) g_POOL[i] /= c;
}

// ---------------------------------------------------------------------------
extern "C" void kernel_launch(void* const* d_in, const int* in_sizes, int n_in,
                              void* d_out, int out_size) {
    const float* obj   = (const float*)d_in[0];
    const float* pred  = (const float*)d_in[1];
    const int*   edges = (const int*)  d_in[2];
    const void*  pind  =               d_in[3];
    const float* W1a   = (const float*)d_in[4];
    const float* b1a   = (const float*)d_in[5];
    const float* W2a   = (const float*)d_in[6];
    const float* b2a   = (const float*)d_in[7];
    const float* W1b   = (const float*)d_in[8];
    const float* b1b   = (const float*)d_in[9];
    const float* W2b   = (const float*)d_in[10];
    const float* b2b   = (const float*)d_in[11];

    float* out     = (float*)d_out;
    float* out_obj = out;                                  // (32,512,128)
    float* out_p   = out + (size_t)NOROW * POUT;           // (32,2048,128)

    float *X, *H, *NT, *POOL, *H2;
    cudaGetSymbolAddress((void**)&X,    g_X);
    cudaGetSymbolAddress((void**)&H,    g_H);
    cudaGetSymbolAddress((void**)&NT,   g_NT);
    cudaGetSymbolAddress((void**)&POOL, g_POOL);
    cudaGetSymbolAddress((void**)&H2,   g_H2);

    // mask dtype sniff + mask build
    detect_kernel<<<1, 256>>>((const unsigned*)pind, NTROW / 4);
    build_mask_kernel<<<NTROW / 256, 256>>>(pind);

    // zero pooled/counts
    zero_kernel<<<(NOROW * HID + 255) / 256, 256>>>();

    // gather concat input
    gather_kernel<<<NTROW, 96>>>(obj, pred, edges);

    // MLP-a (tensor cores)
    tf32_gemm_relu<<<dim3(HID / BN,  NTROW / BM), 256>>>(X, W1a, b1a, H,  NTROW, HID,  IN1);
    tf32_gemm_relu<<<dim3(OUT1 / BN, NTROW / BM), 256>>>(H, W2a, b2a, NT, NTROW, OUT1, HID);

    // scatter-mean + new_p output
    scatter_kernel<<<NTROW, 256>>>(edges, out_p);
    finalize_kernel<<<(NOROW * HID + 255) / 256, 256>>>();

    // MLP-b (final layer writes straight to d_out)
    tf32_gemm_relu<<<dim3(HID / BN,  NOROW / BM), 256>>>(POOL, W1b, b1b, H2, NOROW, HID, HID);
    tf32_gemm_relu<<<dim3(POUT / BN, NOROW / BM), 256>>>(H2,   W2b, b2b, out_obj, NOROW, POUT, HID);
}

// round 7
// speedup vs baseline: 2.5940x; 1.3226x over previous
#include <cuda_runtime.h>
#include <cuda_bf16.h>
#include <stdint.h>

// ---------------------------------------------------------------------------
// GraphTripleConv: B=32, O=512, T=2048, D=128, HIDDEN=256, PRED_OUT=128
// Round 7 (= round 5/6 resubmit after consecutive infra failures):
// tf32 tensor-core GEMMs with
//   - gather fused into GEMM1 A-tile load (g_X eliminated)
//   - scatter-mean + new_p output fused into GEMM2 epilogue (g_NT eliminated)
//   - count normalization fused into GEMM3 A-tile load (finalize eliminated)
// ---------------------------------------------------------------------------

#define B_    32
#define O_    512
#define T_    2048
#define D_    128
#define HID   256
#define POUT  128
#define OUT1  640
#define IN1   384
#define NTROW (B_*T_)   // 65536
#define NOROW (B_*O_)   // 16384

// Scratch (static device globals -- allocation-free)
__device__ float g_H[(size_t)NTROW * HID];
__device__ float g_POOL[(size_t)NOROW * HID];
__device__ float g_CNT[NOROW];
__device__ float g_H2[(size_t)NOROW * HID];
__device__ float g_MASK[NTROW];
__device__ int   g_mode;   // 0=f32, 1=i32, 2=u8/i8, 3=bf16

// ---------------------------------------------------------------------------
// pred_indicators dtype sniffer (values are {0,1} in an unknown dtype)
// ---------------------------------------------------------------------------
__global__ void detect_kernel(const unsigned* __restrict__ w, int nwords) {
    __shared__ int sf32, sbf16, sother;
    if (threadIdx.x == 0) { sf32 = 0; sbf16 = 0; sother = 0; }
    __syncthreads();
    for (int i = threadIdx.x; i < nwords; i += blockDim.x) {
        unsigned v = w[i];
        if (v == 0x3F800000u) sf32 = 1;
        unsigned lo = v & 0xFFFFu, hi = v >> 16;
        bool bfp = (lo == 0u || lo == 0x3F80u) && (hi == 0u || hi == 0x3F80u);
        if (bfp && (lo == 0x3F80u || hi == 0x3F80u)) sbf16 = 1;
        if (v != 0u && v != 1u && !bfp && v != 0x3F800000u) sother = 1;
    }
    __syncthreads();
    if (threadIdx.x == 0) {
        int m;
        if (sf32) m = 0;
        else if (sbf16) m = 3;
        else if (sother) m = 2;
        else m = 1;
        g_mode = m;
    }
}

__global__ void zero_kernel() {
    int i = blockIdx.x * blockDim.x + threadIdx.x;
    if (i < NOROW * HID) g_POOL[i] = 0.0f;
    if (i < NOROW)       g_CNT[i]  = 0.0f;
}

// mask build + count scatter (counts fused here; must run after zero_kernel)
__global__ void build_mask_count_kernel(const void* __restrict__ p,
                                        const int* __restrict__ edges) {
    int i = blockIdx.x * blockDim.x + threadIdx.x;
    if (i >= NTROW) return;
    int mode = g_mode;
    float v;
    if (mode == 0)      v = ((const float*)p)[i];
    else if (mode == 1) v = (float)((const int*)p)[i];
    else if (mode == 2) v = (float)((const unsigned char*)p)[i];
    else                v = __bfloat162float(((const __nv_bfloat16*)p)[i]);
    g_MASK[i] = v;
    if (v != 0.0f) {
        int b = i >> 11;
        atomicAdd(&g_CNT[b * O_ + edges[2 * i]],     v);
        atomicAdd(&g_CNT[b * O_ + edges[2 * i + 1]], v);
    }
}

// ---------------------------------------------------------------------------
// Shared tf32 GEMM machinery
//   BM=BN=128, BK=16, 256 threads = 8 warps (4m x 2n), warp tile 32x64.
// ---------------------------------------------------------------------------
#define BM 128
#define BN 128
#define BK 16
#define AST 20    // A smem row stride (u32)
#define BST 132   // B smem row stride (u32)

__device__ __forceinline__ uint32_t f2tf(float x) {
    uint32_t r;
    asm("cvt.rna.tf32.f32 %0, %1;" : "=r"(r) : "f"(x));
    return r;
}

__device__ __forceinline__ void mma_tf32(float* c, const uint32_t* a,
                                         uint32_t b0, uint32_t b1) {
    asm volatile(
        "mma.sync.aligned.m16n8k8.row.col.f32.tf32.tf32.f32 "
        "{%0,%1,%2,%3}, {%4,%5,%6,%7}, {%8,%9}, {%0,%1,%2,%3};"
        : "+f"(c[0]), "+f"(c[1]), "+f"(c[2]), "+f"(c[3])
        : "r"(a[0]), "r"(a[1]), "r"(a[2]), "r"(a[3]), "r"(b0), "r"(b1));
}

#define STORE_A_TILE(nb, a0, a1, s0, s1)                                          \
    *(uint4*)&As[nb][ar0][ac0] = make_uint4(f2tf((a0).x*(s0)), f2tf((a0).y*(s0)), \
                                            f2tf((a0).z*(s0)), f2tf((a0).w*(s0)));\
    *(uint4*)&As[nb][ar1][ac0] = make_uint4(f2tf((a1).x*(s1)), f2tf((a1).y*(s1)), \
                                            f2tf((a1).z*(s1)), f2tf((a1).w*(s1)));

#define STORE_B_TILE(nb, b0, b1)                                                  \
    *(uint4*)&Bs[nb][br0][bc0] = make_uint4(f2tf((b0).x), f2tf((b0).y),           \
                                            f2tf((b0).z), f2tf((b0).w));          \
    *(uint4*)&Bs[nb][br1][bc1] = make_uint4(f2tf((b1).x), f2tf((b1).y),           \
                                            f2tf((b1).z), f2tf((b1).w));

#define COMPUTE_TILE(buf)                                                         \
    _Pragma("unroll")                                                             \
    for (int ks = 0; ks < 2; ks++) {                                              \
        const int kk = ks * 8;                                                    \
        uint32_t a[2][4];                                                         \
        _Pragma("unroll")                                                         \
        for (int mf = 0; mf < 2; mf++) {                                          \
            const int r = m0 + mf * 16 + g;                                       \
            a[mf][0] = As[buf][r][kk + i4];                                       \
            a[mf][1] = As[buf][r + 8][kk + i4];                                   \
            a[mf][2] = As[buf][r][kk + i4 + 4];                                   \
            a[mf][3] = As[buf][r + 8][kk + i4 + 4];                               \
        }                                                                         \
        _Pragma("unroll")                                                         \
        for (int nf = 0; nf < 8; nf++) {                                          \
            const int cc = n0 + nf * 8 + g;                                       \
            const uint32_t b0 = Bs[buf][kk + i4][cc];                             \
            const uint32_t b1 = Bs[buf][kk + i4 + 4][cc];                         \
            mma_tf32(c[0][nf], a[0], b0, b1);                                     \
            mma_tf32(c[1][nf], a[1], b0, b1);                                     \
        }                                                                         \
    }

#define GEMM_COMMON_SETUP()                                                       \
    const int tid  = threadIdx.x;                                                 \
    const int warp = tid >> 5;                                                    \
    const int lane = tid & 31;                                                    \
    const int g    = lane >> 2;                                                   \
    const int i4   = lane & 3;                                                    \
    const int m0   = (warp & 3) * 32;                                             \
    const int n0   = (warp >> 2) * 64;                                            \
    const int rowBase = blockIdx.y * BM;                                          \
    const int colBase = blockIdx.x * BN;                                          \
    const int ar0 = tid >> 2,  ac0 = (tid & 3) << 2;                              \
    const int ar1 = 64 + (tid >> 2);                                              \
    const int br0 = tid >> 5,  bc0 = (tid & 31) << 2;                             \
    const int br1 = 8 + (tid >> 5), bc1 = bc0;                                    \
    float c[2][8][4];                                                             \
    _Pragma("unroll")                                                             \
    for (int mf = 0; mf < 2; mf++)                                                \
        _Pragma("unroll")                                                         \
        for (int nf = 0; nf < 8; nf++)                                            \
            _Pragma("unroll")                                                     \
            for (int q = 0; q < 4; q++) c[mf][nf][q] = 0.0f;

// ---------------------------------------------------------------------------
// GEMM generic: C = relu(A*rowscale @ B + bias); rowscale = 1/max(cnt,1) or 1
// ---------------------------------------------------------------------------
__global__ void __launch_bounds__(256, 2)
tf32_gemm_relu(const float* __restrict__ A, const float* __restrict__ B,
               const float* __restrict__ bias, float* __restrict__ C,
               int M, int N, int K, const float* __restrict__ cnt) {
    __shared__ uint32_t As[2][BM][AST];
    __shared__ uint32_t Bs[2][BK][BST];
    GEMM_COMMON_SETUP();

    const float s0 = cnt ? (1.0f / fmaxf(cnt[rowBase + ar0], 1.0f)) : 1.0f;
    const float s1 = cnt ? (1.0f / fmaxf(cnt[rowBase + ar1], 1.0f)) : 1.0f;

    {
        float4 a0 = *(const float4*)(A + (size_t)(rowBase + ar0) * K + ac0);
        float4 a1 = *(const float4*)(A + (size_t)(rowBase + ar1) * K + ac0);
        float4 b0 = *(const float4*)(B + (size_t)br0 * N + colBase + bc0);
        float4 b1 = *(const float4*)(B + (size_t)br1 * N + colBase + bc1);
        STORE_A_TILE(0, a0, a1, s0, s1);
        STORE_B_TILE(0, b0, b1);
    }
    __syncthreads();

    int buf = 0;
    for (int k0 = 0; k0 < K; k0 += BK) {
        const bool has_next = (k0 + BK < K);
        float4 an0, an1, bn0, bn1;
        if (has_next) {
            const int kn = k0 + BK;
            an0 = *(const float4*)(A + (size_t)(rowBase + ar0) * K + kn + ac0);
            an1 = *(const float4*)(A + (size_t)(rowBase + ar1) * K + kn + ac0);
            bn0 = *(const float4*)(B + (size_t)(kn + br0) * N + colBase + bc0);
            bn1 = *(const float4*)(B + (size_t)(kn + br1) * N + colBase + bc1);
        }
        COMPUTE_TILE(buf);
        if (has_next) {
            const int nb = buf ^ 1;
            STORE_A_TILE(nb, an0, an1, s0, s1);
            STORE_B_TILE(nb, bn0, bn1);
        }
        __syncthreads();
        buf ^= 1;
    }

#pragma unroll
    for (int nf = 0; nf < 8; nf++) {
        const int col = colBase + n0 + nf * 8 + 2 * i4;
        const float bx = bias[col], by = bias[col + 1];
#pragma unroll
        for (int mf = 0; mf < 2; mf++) {
            const int r0 = rowBase + m0 + mf * 16 + g;
            float2 v0, v1;
            v0.x = fmaxf(c[mf][nf][0] + bx, 0.0f);
            v0.y = fmaxf(c[mf][nf][1] + by, 0.0f);
            v1.x = fmaxf(c[mf][nf][2] + bx, 0.0f);
            v1.y = fmaxf(c[mf][nf][3] + by, 0.0f);
            *(float2*)(C + (size_t)r0 * N + col)       = v0;
            *(float2*)(C + (size_t)(r0 + 8) * N + col) = v1;
        }
    }
}

// ---------------------------------------------------------------------------
// GEMM1: H = relu(gather(X) @ W1a + b1a), gather fused into A-tile load.
//   A row t = [obj[b,s] | pred[t] | obj[b,o]], K=384 fixed.
// ---------------------------------------------------------------------------
__global__ void __launch_bounds__(256, 2)
tf32_gemm_gather_relu(const float* __restrict__ obj, const float* __restrict__ pred,
                      const int* __restrict__ edges,
                      const float* __restrict__ B, const float* __restrict__ bias,
                      float* __restrict__ C) {
    __shared__ uint32_t As[2][BM][AST];
    __shared__ uint32_t Bs[2][BK][BST];
    const int N = HID, K = IN1;
    GEMM_COMMON_SETUP();

    // per-thread fixed rows -> edge lookups hoisted out of the k-loop
    const int t0 = rowBase + ar0, t1 = rowBase + ar1;
    const int b0i = t0 >> 11,     b1i = t1 >> 11;
    const int sidx0 = b0i * O_ + edges[2 * t0];
    const int oidx0 = b0i * O_ + edges[2 * t0 + 1];
    const int sidx1 = b1i * O_ + edges[2 * t1];
    const int oidx1 = b1i * O_ + edges[2 * t1 + 1];

#define LOAD_GATHER(kc, a0v, a1v)                                                 \
    {                                                                             \
        const int gcol = (kc) + ac0;   /* whole BK tile within one segment */     \
        const float *p0, *p1;                                                     \
        if (gcol < 128) {                                                         \
            p0 = obj + ((size_t)sidx0 << 7) + gcol;                               \
            p1 = obj + ((size_t)sidx1 << 7) + gcol;                               \
        } else if (gcol < 256) {                                                  \
            p0 = pred + ((size_t)t0 << 7) + (gcol - 128);                         \
            p1 = pred + ((size_t)t1 << 7) + (gcol - 128);                         \
        } else {                                                                  \
            p0 = obj + ((size_t)oidx0 << 7) + (gcol - 256);                       \
            p1 = obj + ((size_t)oidx1 << 7) + (gcol - 256);                       \
        }                                                                         \
        a0v = *(const float4*)p0;                                                 \
        a1v = *(const float4*)p1;                                                 \
    }

    {
        float4 a0, a1;
        LOAD_GATHER(0, a0, a1);
        float4 b0 = *(const float4*)(B + (size_t)br0 * N + colBase + bc0);
        float4 b1 = *(const float4*)(B + (size_t)br1 * N + colBase + bc1);
        STORE_A_TILE(0, a0, a1, 1.0f, 1.0f);
        STORE_B_TILE(0, b0, b1);
    }
    __syncthreads();

    int buf = 0;
    for (int k0 = 0; k0 < K; k0 += BK) {
        const bool has_next = (k0 + BK < K);
        float4 an0, an1, bn0, bn1;
        if (has_next) {
            const int kn = k0 + BK;
            LOAD_GATHER(kn, an0, an1);
            bn0 = *(const float4*)(B + (size_t)(kn + br0) * N + colBase + bc0);
            bn1 = *(const float4*)(B + (size_t)(kn + br1) * N + colBase + bc1);
        }
        COMPUTE_TILE(buf);
        if (has_next) {
            const int nb = buf ^ 1;
            STORE_A_TILE(nb, an0, an1, 1.0f, 1.0f);
            STORE_B_TILE(nb, bn0, bn1);
        }
        __syncthreads();
        buf ^= 1;
    }
#undef LOAD_GATHER

#pragma unroll
    for (int nf = 0; nf < 8; nf++) {
        const int col = colBase + n0 + nf * 8 + 2 * i4;
        const float bx = bias[col], by = bias[col + 1];
#pragma unroll
        for (int mf = 0; mf < 2; mf++) {
            const int r0 = rowBase + m0 + mf * 16 + g;
            float2 v0, v1;
            v0.x = fmaxf(c[mf][nf][0] + bx, 0.0f);
            v0.y = fmaxf(c[mf][nf][1] + by, 0.0f);
            v1.x = fmaxf(c[mf][nf][2] + bx, 0.0f);
            v1.y = fmaxf(c[mf][nf][3] + by, 0.0f);
            *(float2*)(C + (size_t)r0 * N + col)       = v0;
            *(float2*)(C + (size_t)(r0 + 8) * N + col) = v1;
        }
    }
}

// ---------------------------------------------------------------------------
// GEMM2: NT = relu(H @ W2a + b2a) with fused epilogue:
//   col tiles 0,128   -> atomic scatter new_s*m into g_POOL
//   col tile  256     -> new_p straight to d_out
//   col tiles 384,512 -> atomic scatter new_o*m into g_POOL
// NT is never materialized.
// ---------------------------------------------------------------------------
__global__ void __launch_bounds__(256, 2)
tf32_gemm_scatter(const float* __restrict__ A, const float* __restrict__ B,
                  const float* __restrict__ bias, const int* __restrict__ edges,
                  float* __restrict__ out_p) {
    __shared__ uint32_t As[2][BM][AST];
    __shared__ uint32_t Bs[2][BK][BST];
    const int N = OUT1, K = HID;
    GEMM_COMMON_SETUP();

    {
        float4 a0 = *(const float4*)(A + (size_t)(rowBase + ar0) * K + ac0);
        float4 a1 = *(const float4*)(A + (size_t)(rowBase + ar1) * K + ac0);
        float4 b0 = *(const float4*)(B + (size_t)br0 * N + colBase + bc0);
        float4 b1 = *(const float4*)(B + (size_t)br1 * N + colBase + bc1);
        STORE_A_TILE(0, a0, a1, 1.0f, 1.0f);
        STORE_B_TILE(0, b0, b1);
    }
    __syncthreads();

    int buf = 0;
    for (int k0 = 0; k0 < K; k0 += BK) {
        const bool has_next = (k0 + BK < K);
        float4 an0, an1, bn0, bn1;
        if (has_next) {
            const int kn = k0 + BK;
            an0 = *(const float4*)(A + (size_t)(rowBase + ar0) * K + kn + ac0);
            an1 = *(const float4*)(A + (size_t)(rowBase + ar1) * K + kn + ac0);
            bn0 = *(const float4*)(B + (size_t)(kn + br0) * N + colBase + bc0);
            bn1 = *(const float4*)(B + (size_t)(kn + br1) * N + colBase + bc1);
        }
        COMPUTE_TILE(buf);
        if (has_next) {
            const int nb = buf ^ 1;
            STORE_A_TILE(nb, an0, an1, 1.0f, 1.0f);
            STORE_B_TILE(nb, bn0, bn1);
        }
        __syncthreads();
        buf ^= 1;
    }

    // ---- fused scatter epilogue
    const int mode = (colBase < 256) ? 0 : ((colBase == 256) ? 1 : 2);

    // per-thread row metadata: rows rowBase + m0 + {0,8,16,24} + g
    float  mk[4];
    size_t pb[4];
    int    tr[4];
#pragma unroll
    for (int q = 0; q < 4; q++) {
        const int r = rowBase + m0 + q * 8 + g;
        tr[q] = r;
        if (mode != 1) {
            mk[q] = g_MASK[r];
            const int b  = r >> 11;
            const int ei = (mode == 0) ? edges[2 * r] : edges[2 * r + 1];
            pb[q] = (size_t)(b * O_ + ei) * HID;
        }
    }
    const int pcb = (mode == 0) ? colBase : colBase - 384;

#pragma unroll
    for (int nf = 0; nf < 8; nf++) {
        const int local = n0 + nf * 8 + 2 * i4;
        const float bx = bias[colBase + local], by = bias[colBase + local + 1];
#pragma unroll
        for (int mf = 0; mf < 2; mf++) {
#pragma unroll
            for (int h = 0; h < 2; h++) {
                const int q = mf * 2 + h;
                float vx = fmaxf(c[mf][nf][2 * h]     + bx, 0.0f);
                float vy = fmaxf(c[mf][nf][2 * h + 1] + by, 0.0f);
                if (mode == 1) {
                    float2 v = make_float2(vx, vy);
                    *(float2*)(out_p + (size_t)tr[q] * POUT + local) = v;
                } else {
                    const float m = mk[q];
                    if (m != 0.0f) {
                        atomicAdd(&g_POOL[pb[q] + pcb + local],     vx * m);
                        atomicAdd(&g_POOL[pb[q] + pcb + local + 1], vy * m);
                    }
                }
            }
        }
    }
}

// ---------------------------------------------------------------------------
extern "C" void kernel_launch(void* const* d_in, const int* in_sizes, int n_in,
                              void* d_out, int out_size) {
    const float* obj   = (const float*)d_in[0];
    const float* pred  = (const float*)d_in[1];
    const int*   edges = (const int*)  d_in[2];
    const void*  pind  =               d_in[3];
    const float* W1a   = (const float*)d_in[4];
    const float* b1a   = (const float*)d_in[5];
    const float* W2a   = (const float*)d_in[6];
    const float* b2a   = (const float*)d_in[7];
    const float* W1b   = (const float*)d_in[8];
    const float* b1b   = (const float*)d_in[9];
    const float* W2b   = (const float*)d_in[10];
    const float* b2b   = (const float*)d_in[11];

    float* out     = (float*)d_out;
    float* out_obj = out;                                  // (32,512,128)
    float* out_p   = out + (size_t)NOROW * POUT;           // (32,2048,128)

    float *H, *POOL, *CNT, *H2;
    cudaGetSymbolAddress((void**)&H,    g_H);
    cudaGetSymbolAddress((void**)&POOL, g_POOL);
    cudaGetSymbolAddress((void**)&CNT,  g_CNT);
    cudaGetSymbolAddress((void**)&H2,   g_H2);

    // prep: zero pooled/counts, sniff mask dtype, build mask + counts
    zero_kernel<<<(NOROW * HID + 255) / 256, 256>>>();
    detect_kernel<<<1, 256>>>((const unsigned*)pind, NTROW / 4);
    build_mask_count_kernel<<<NTROW / 256, 256>>>(pind, edges);

    // GEMM1: H = relu(gather @ W1a + b1a)       [65536 x 256, K=384]
    tf32_gemm_gather_relu<<<dim3(HID / BN, NTROW / BM), 256>>>(
        obj, pred, edges, W1a, b1a, H);

    // GEMM2: fused scatter-mean accumulate + new_p output  [65536 x 640, K=256]
    tf32_gemm_scatter<<<dim3(OUT1 / BN, NTROW / BM), 256>>>(
        H, W2a, b2a, edges, out_p);

    // GEMM3: H2 = relu((pool/cnt) @ W1b + b1b)  [16384 x 256, K=256]
    tf32_gemm_relu<<<dim3(HID / BN, NOROW / BM), 256>>>(
        POOL, W1b, b1b, H2, NOROW, HID, HID, CNT);

    // GEMM4: out_obj = relu(H2 @ W2b + b2b)     [16384 x 128, K=256]
    tf32_gemm_relu<<<dim3(POUT / BN, NOROW / BM), 256>>>(
        H2, W2b, b2b, out_obj, NOROW, POUT, HID, nullptr);
}